// round 2
// baseline (speedup 1.0000x reference)
#include <cuda_runtime.h>
#include <math.h>

// Problem constants (B=8, C=3, H=W=512, P=64, K=16)
#define BN        512          // B*N patches
#define DD        12288        // C*P*P
#define KR        16           // low rank
#define TRI       136          // 16*17/2
#define T1        256          // threads in pass1 CTA
#define RPT       48           // rows per thread = DD/T1
#define NW        8            // warps per pass1 CTA
#define BBLK      672          // boundary blocks: 672*256 = 172032 pairs
#define GCONST    22583.833392038037f   // d * ln(2*pi)

// Static scratch (allowed: __device__ globals, no runtime allocation)
__device__ float g_tri[BN][NW][TRI];
__device__ float g_wv [BN][NW][KR];
__device__ float g_sc [BN][NW][6];   // rdr, logdetD, sumV2, sumSig, sumRelu2, minSig
__device__ float g_nll[BN];
__device__ float g_bp [BBLK];

// ---------------------------------------------------------------------------
// Pass 1: one CTA per patch. Each thread owns 48 rows (stride 256), keeps the
// full 136-entry symmetric VtD^-1V triangle + w[16] in registers, fused with
// residual quad form, logdet, and all sigma/V statistics. Warp butterfly
// reduction, per-warp partials to global scratch.
//
// Identity used: quad = r^T D^-1 r - w^T M^-1 w  with w = V^T D^-1 r,
// so V is read EXACTLY ONCE (no second pass for the correction term).
// ---------------------------------------------------------------------------
__global__ void __launch_bounds__(T1, 1) pass1_kernel(
    const float* __restrict__ x0, const float* __restrict__ mu,
    const float* __restrict__ sigma, const float* __restrict__ V)
{
    const int p = blockIdx.x;
    const int t = threadIdx.x;
    const int b  = p >> 6;
    const int n  = p & 63;
    const int gy = n >> 3;
    const int gx = n & 7;

    const float*  __restrict__ mup = mu    + (size_t)p * DD;
    const float*  __restrict__ sgp = sigma + (size_t)p * DD;
    const float4* __restrict__ vp  = (const float4*)V + (size_t)p * (DD * 4);
    // x0 pixel (b,c, gy*64+py, gx*64+px); base excludes c*512*512 and py*512+px
    const float*  __restrict__ xp  = x0 + (size_t)b * 3 * 262144
                                        + (size_t)(gy * 64) * 512 + gx * 64;

    float tri[TRI];
    float wv[KR];
#pragma unroll
    for (int q = 0; q < TRI; q++) tri[q] = 0.0f;
#pragma unroll
    for (int q = 0; q < KR; q++) wv[q] = 0.0f;
    float rdr = 0.0f, ld = 0.0f, sv2 = 0.0f, ssg = 0.0f, srel = 0.0f;
    float smin = 3.402823466e38f;

    // Prefetch row 0
    int i = t;
    float  sg = sgp[i];
    float  m  = mup[i];
    float  xx = xp[(i >> 12) * 262144 + ((i >> 6) & 63) * 512 + (i & 63)];
    float4 v0 = vp[i * 4 + 0], v1 = vp[i * 4 + 1], v2 = vp[i * 4 + 2], v3 = vp[i * 4 + 3];

#pragma unroll 1
    for (int j = 0; j < RPT; j++) {
        const float  csg = sg, cm = m, cx = xx;
        const float4 c0 = v0, c1 = v1, c2 = v2, c3 = v3;
        if (j + 1 < RPT) {                       // prefetch next row
            i = t + ((j + 1) << 8);
            sg = sgp[i];
            m  = mup[i];
            xx = xp[(i >> 12) * 262144 + ((i >> 6) & 63) * 512 + (i & 63)];
            v0 = vp[i * 4 + 0]; v1 = vp[i * 4 + 1];
            v2 = vp[i * 4 + 2]; v3 = vp[i * 4 + 3];
        }

        const float s   = rsqrtf(csg);           // sigma^{-1/2}
        const float r   = cx - cm;
        const float gsv = s * r;                 // sigma^{-1/2} * r
        rdr  = fmaf(gsv, gsv, rdr);              // r^T D^-1 r
        ld  += __logf(csg);                      // log det D
        ssg += csg;
        const float u = fmaxf(0.3f - csg, 0.0f);
        srel = fmaf(u, u, srel);
        smin = fminf(smin, csg);

        float a[KR];                             // a = V_row * s  -> a_k a_j = V_k V_j / sigma
        a[0]=c0.x*s; a[1]=c0.y*s; a[2]=c0.z*s; a[3]=c0.w*s;
        a[4]=c1.x*s; a[5]=c1.y*s; a[6]=c1.z*s; a[7]=c1.w*s;
        a[8]=c2.x*s; a[9]=c2.y*s; a[10]=c2.z*s; a[11]=c2.w*s;
        a[12]=c3.x*s; a[13]=c3.y*s; a[14]=c3.z*s; a[15]=c3.w*s;

        float t2 = 0.0f;
#pragma unroll
        for (int k = 0; k < KR; k++) {
            const float ak = a[k];
            wv[k] = fmaf(ak, gsv, wv[k]);        // V^T D^-1 r
            t2    = fmaf(ak, ak, t2);            // for sum(V^2): V^2 = sigma * a^2
#pragma unroll
            for (int q = 0; q <= k; q++)
                tri[(k * (k + 1)) / 2 + q] = fmaf(ak, a[q], tri[(k * (k + 1)) / 2 + q]);
        }
        sv2 = fmaf(csg, t2, sv2);
    }

    // Warp butterfly reduction of all accumulators
#pragma unroll
    for (int off = 16; off > 0; off >>= 1) {
#pragma unroll
        for (int q = 0; q < TRI; q++) tri[q] += __shfl_xor_sync(0xffffffffu, tri[q], off);
#pragma unroll
        for (int q = 0; q < KR; q++) wv[q] += __shfl_xor_sync(0xffffffffu, wv[q], off);
        rdr  += __shfl_xor_sync(0xffffffffu, rdr,  off);
        ld   += __shfl_xor_sync(0xffffffffu, ld,   off);
        sv2  += __shfl_xor_sync(0xffffffffu, sv2,  off);
        ssg  += __shfl_xor_sync(0xffffffffu, ssg,  off);
        srel += __shfl_xor_sync(0xffffffffu, srel, off);
        smin  = fminf(smin, __shfl_xor_sync(0xffffffffu, smin, off));
    }

    const int w = t >> 5, l = t & 31;
    for (int q = l; q < TRI; q += 32) g_tri[p][w][q] = tri[q];
    if (l < KR) g_wv[p][w][l] = wv[l];
    if (l == 0) {
        g_sc[p][w][0] = rdr;  g_sc[p][w][1] = ld;
        g_sc[p][w][2] = sv2;  g_sc[p][w][3] = ssg;
        g_sc[p][w][4] = srel; g_sc[p][w][5] = smin;
    }
}

// ---------------------------------------------------------------------------
// Pass 2: one CTA per patch. Sum warp partials, M = VtDiV + (1+1e-6)I,
// 16x16 Cholesky (warp 0), forward solve, per-patch NLL.
// ---------------------------------------------------------------------------
__global__ void __launch_bounds__(256) pass2_kernel()
{
    const int p = blockIdx.x;
    const int t = threadIdx.x;
    __shared__ float Ms[16][17];
    __shared__ float sw[16];
    __shared__ float srd[2];

    const int tk = t >> 4, tj = t & 15;
    if (tj <= tk) {
        const int idx = (tk * (tk + 1)) / 2 + tj;
        float s = 0.0f;
#pragma unroll
        for (int w = 0; w < NW; w++) s += g_tri[p][w][idx];
        if (tj == tk) s += 1.0f + 1e-6f;
        Ms[tk][tj] = s;
        Ms[tj][tk] = s;
    }
    if (t < 16) {
        float s = 0.0f;
#pragma unroll
        for (int w = 0; w < NW; w++) s += g_wv[p][w][t];
        sw[t] = s;
    }
    if (t == 1) {   // (tk=0,tj=1): idle in triangle fill
        float s = 0.0f;
#pragma unroll
        for (int w = 0; w < NW; w++) s += g_sc[p][w][0];
        srd[0] = s;
    }
    if (t == 2) {   // (tk=0,tj=2): idle in triangle fill
        float s = 0.0f;
#pragma unroll
        for (int w = 0; w < NW; w++) s += g_sc[p][w][1];
        srd[1] = s;
    }
    __syncthreads();

    if (t < 32) {
        // In-place Cholesky of lower triangle, column by column
        for (int j = 0; j < 16; j++) {
            if (t == j) Ms[j][j] = sqrtf(Ms[j][j]);
            __syncwarp();
            if (t > j && t < 16) Ms[t][j] = Ms[t][j] / Ms[j][j];
            __syncwarp();
            if (t > j && t < 16) {
                const float lij = Ms[t][j];
                for (int q = j + 1; q <= t; q++)
                    Ms[t][q] -= lij * Ms[q][j];
            }
            __syncwarp();
        }
        __syncwarp();
        if (t == 0) {
            // forward solve L y = w ;  w^T M^-1 w = ||y||^2
            float y[16];
            float yy = 0.0f, ldm = 0.0f;
            for (int r = 0; r < 16; r++) {
                float acc = sw[r];
                for (int q = 0; q < r; q++) acc -= Ms[r][q] * y[q];
                y[r] = acc / Ms[r][r];
                yy  = fmaf(y[r], y[r], yy);
                ldm += __logf(Ms[r][r]);
            }
            const float quad = srd[0] - yy;
            const float nll  = 0.5f * (quad + srd[1] + 2.0f * ldm + GCONST)
                               * (1.0f / (float)DD);
            g_nll[p] = nll;
        }
    }
}

// ---------------------------------------------------------------------------
// Boundary loss over unpatchify(mu): 7 y-boundaries + 7 x-boundaries,
// 172032 squared diffs total; per-block partial sums.
// ---------------------------------------------------------------------------
__global__ void __launch_bounds__(256) boundary_kernel(const float* __restrict__ mu)
{
    int e = blockIdx.x * 256 + threadIdx.x;     // [0, 172032)
    int q = e;
    const bool isdy = (q < 86016);
    if (!isdy) q -= 86016;
    const int xw = q & 511;  q >>= 9;
    const int c  = q % 3;    q /= 3;
    const int b  = q & 7;    q >>= 3;
    const int tb = q;                            // 0..6 -> boundary at 64*(tb+1)

    size_t ia, ib;
    if (isdy) {
        const int gx = xw >> 6, px = xw & 63;
        ia = (size_t)(b * 64 + (tb + 1) * 8 + gx) * DD + c * 4096 + px;          // py=0
        ib = (size_t)(b * 64 +  tb      * 8 + gx) * DD + c * 4096 + 4032 + px;   // py=63
    } else {
        const int gy = xw >> 6, py = xw & 63;
        ia = (size_t)(b * 64 + gy * 8 + tb + 1) * DD + c * 4096 + py * 64;       // px=0
        ib = (size_t)(b * 64 + gy * 8 + tb    ) * DD + c * 4096 + py * 64 + 63;  // px=63
    }
    const float dif = mu[ia] - mu[ib];
    float v = dif * dif;

#pragma unroll
    for (int off = 16; off > 0; off >>= 1) v += __shfl_xor_sync(0xffffffffu, v, off);
    __shared__ float sred[8];
    if ((threadIdx.x & 31) == 0) sred[threadIdx.x >> 5] = v;
    __syncthreads();
    if (threadIdx.x < 8) {
        float s = sred[threadIdx.x];
#pragma unroll
        for (int off = 4; off > 0; off >>= 1) s += __shfl_xor_sync(0xffu, s, off);
        if (threadIdx.x == 0) g_bp[blockIdx.x] = s;
    }
}

// ---------------------------------------------------------------------------
// Final reduction: combine everything into the 7 output scalars.
// ---------------------------------------------------------------------------
__global__ void __launch_bounds__(512) final_kernel(float* __restrict__ out, int out_size)
{
    const int t = threadIdx.x;       // 512 threads
    float nl = g_nll[t];
    float bs = (t < BBLK) ? g_bp[t] : 0.0f;
    if (t + 512 < BBLK) bs += g_bp[t + 512];

    float sv2 = 0.0f, ssg = 0.0f, srel = 0.0f, rmin = 3.402823466e38f;
#pragma unroll
    for (int q = 0; q < 8; q++) {
        const int slot = t + q * 512;            // 0..4095 = 512 patches * 8 warps
        const int pp = slot >> 3, w = slot & 7;
        sv2  += g_sc[pp][w][2];
        ssg  += g_sc[pp][w][3];
        srel += g_sc[pp][w][4];
        rmin  = fminf(rmin, g_sc[pp][w][5]);
    }

#pragma unroll
    for (int off = 16; off > 0; off >>= 1) {
        nl   += __shfl_xor_sync(0xffffffffu, nl,   off);
        bs   += __shfl_xor_sync(0xffffffffu, bs,   off);
        sv2  += __shfl_xor_sync(0xffffffffu, sv2,  off);
        ssg  += __shfl_xor_sync(0xffffffffu, ssg,  off);
        srel += __shfl_xor_sync(0xffffffffu, srel, off);
        rmin  = fminf(rmin, __shfl_xor_sync(0xffffffffu, rmin, off));
    }
    __shared__ float sm[16][6];
    if ((t & 31) == 0) {
        const int w = t >> 5;
        sm[w][0] = nl; sm[w][1] = bs; sm[w][2] = sv2;
        sm[w][3] = ssg; sm[w][4] = srel; sm[w][5] = rmin;
    }
    __syncthreads();
    if (t < 16) {
        float a0 = sm[t][0], a1 = sm[t][1], a2 = sm[t][2];
        float a3 = sm[t][3], a4 = sm[t][4], a5 = sm[t][5];
#pragma unroll
        for (int off = 8; off > 0; off >>= 1) {
            a0 += __shfl_xor_sync(0xffffu, a0, off);
            a1 += __shfl_xor_sync(0xffffu, a1, off);
            a2 += __shfl_xor_sync(0xffffu, a2, off);
            a3 += __shfl_xor_sync(0xffffu, a3, off);
            a4 += __shfl_xor_sync(0xffffu, a4, off);
            a5  = fminf(a5, __shfl_xor_sync(0xffffu, a5, off));
        }
        if (t == 0) {
            const float recon = a0 * (1.0f / 512.0f);
            const float bnd   = a1 * (1.0f / 172032.0f);     // sum / (12288 * 14)
            const float rank  = a2 * (1.0f / 100663296.0f);  // mean(V^2)
            const float msig  = a3 * (1.0f / 6291456.0f);
            const float sgp2  = a4 * (1.0f / 6291456.0f);
            out[0] = recon + 0.1f * bnd + 0.01f * rank + 0.05f * sgp2;
            out[1] = recon;
            out[2] = bnd;
            out[3] = rank;
            out[4] = sgp2;
            out[5] = msig;
            out[6] = a5;
        }
    }
    __syncthreads();
    // zero-fill any extra output slots
    for (int q = t + ((t >= 7) ? 0 : 512); q < out_size; q += 512)
        if (q >= 7) out[q] = 0.0f;
}

// ---------------------------------------------------------------------------
extern "C" void kernel_launch(void* const* d_in, const int* in_sizes, int n_in,
                              void* d_out, int out_size)
{
    // Identify V by its unique size; remaining inputs keep metadata order
    // (x0, mu, sigma all have 6291456 elements).
    int vi = 3;
    for (int idx = 0; idx < n_in; idx++)
        if (in_sizes[idx] == 100663296) vi = idx;
    const float* rest[3] = {nullptr, nullptr, nullptr};
    int m = 0;
    for (int idx = 0; idx < n_in && m < 3; idx++)
        if (idx != vi) rest[m++] = (const float*)d_in[idx];
    const float* x0 = rest[0];
    const float* mu = rest[1];
    const float* sg = rest[2];
    const float* V  = (const float*)d_in[vi];

    pass1_kernel<<<BN, T1>>>(x0, mu, sg, V);
    boundary_kernel<<<BBLK, 256>>>(mu);
    pass2_kernel<<<BN, 256>>>();
    final_kernel<<<1, 512>>>((float*)d_out, out_size);
}

// round 4
// speedup vs baseline: 1.1555x; 1.1555x over previous
#include <cuda_runtime.h>
#include <math.h>

// Problem constants (B=8, C=3, H=W=512, P=64, K=16)
#define BN        512          // B*N patches
#define DD        12288        // C*P*P
#define KR        16           // low rank
#define T1        256          // threads in pass1 CTA (128 row-pairs)
#define ITERS     96           // 12288 rows / 128 pairs
#define NW        8            // warps per pass1 CTA
#define NTRI      72           // per-lane triangle entries (36 small + 28 mixed + 8 fixed)
#define BBLK      672          // boundary blocks: 672*256 = 172032 pairs
#define GCONST    22583.833392038037f   // d * ln(2*pi)

// Static scratch
__device__ float g_nll[BN];
__device__ float g_sc [BN][6];   // rdr, ld, sv2, ssg, srel, smin
__device__ float g_bp [BBLK];

// ---------------------------------------------------------------------------
// Pass 1 (fused with pass 2): one CTA per patch, 128 lane-PAIRS.
// Both lanes of a pair process the SAME row; odd lane works on the index-
// reversed vector b[j] = a[15-j], so one static 72-entry list covers the full
// 136-entry V^T D^-1 V triangle across the pair:
//   even lane (b=a):        small tri (k<=7), mixed k+q<15, anti-diag k+q=15
//   odd  lane (b=a o rev):  big tri (both>=8), mixed k+q>15, anti-diag (dup x0.5)
// Then smem merge, 16x16 Cholesky, forward solve, per-patch NLL — all in-CTA.
// Identity: quad = r^T D^-1 r - w^T M^-1 w,  w = V^T D^-1 r  (V read ONCE).
// ---------------------------------------------------------------------------
__global__ void __launch_bounds__(T1, 2) pass1_kernel(
    const float* __restrict__ x0, const float* __restrict__ mu,
    const float* __restrict__ sigma, const float* __restrict__ V)
{
    const int pat = blockIdx.x;
    const int t   = threadIdx.x;
    const int par = t & 1;             // lane parity within pair
    const int pr  = t >> 1;            // pair id: 0..127
    const int b_  = pat >> 6;
    const int n   = pat & 63;
    const int gy  = n >> 3;
    const int gx  = n & 7;

    const float* __restrict__ mup = mu    + (size_t)pat * DD;
    const float* __restrict__ sgp = sigma + (size_t)pat * DD;
    const float* __restrict__ vp  = V     + (size_t)pat * DD * KR;
    const float* __restrict__ xp  = x0 + (size_t)b_ * 3 * 262144
                                       + (size_t)(gy * 64) * 512 + gx * 64;

    float tri[NTRI];
    float wvh[8];
#pragma unroll
    for (int q = 0; q < NTRI; q++) tri[q] = 0.0f;
#pragma unroll
    for (int q = 0; q < 8; q++) wvh[q] = 0.0f;
    float rdr = 0.0f, ld = 0.0f, sv2 = 0.0f, ssg = 0.0f, srel = 0.0f;
    float smin = 3.402823466e38f;

#pragma unroll 1
    for (int it = 0; it < ITERS; it++) {
        const int i = pr + (it << 7);                   // row index 0..12287
        // loads: both lanes load the row scalars (broadcast); V half per parity
        const float csg = sgp[i];
        const float cm  = mup[i];
        const float cx  = xp[(i >> 12) * 262144 + ((i >> 6) & 63) * 512 + (i & 63)];
        const float4 va = *(const float4*)(vp + (size_t)i * KR + par * 8);
        const float4 vb = *(const float4*)(vp + (size_t)i * KR + par * 8 + 4);

        const float s   = rsqrtf(csg);
        const float r   = cx - cm;
        const float gsv = s * r;
        rdr  = fmaf(gsv, gsv, rdr);
        ld  += __logf(csg);
        ssg += csg;
        const float u = fmaxf(0.3f - csg, 0.0f);
        srel = fmaf(u, u, srel);
        smin = fminf(smin, csg);

        // raw V^2 partial (own half only -> no duplication across the pair)
        float t2 = 0.0f;
        t2 = fmaf(va.x, va.x, t2); t2 = fmaf(va.y, va.y, t2);
        t2 = fmaf(va.z, va.z, t2); t2 = fmaf(va.w, va.w, t2);
        t2 = fmaf(vb.x, vb.x, t2); t2 = fmaf(vb.y, vb.y, t2);
        t2 = fmaf(vb.z, vb.z, t2); t2 = fmaf(vb.w, vb.w, t2);
        sv2 += t2;

        float own[8];
        own[0]=va.x*s; own[1]=va.y*s; own[2]=va.z*s; own[3]=va.w*s;
        own[4]=vb.x*s; own[5]=vb.y*s; own[6]=vb.z*s; own[7]=vb.w*s;

        // build b: even lane b = a ; odd lane b[j] = a[15-j]
        float b[16];
#pragma unroll
        for (int j = 0; j < 8; j++) b[j] = par ? own[7 - j] : own[j];
#pragma unroll
        for (int j = 0; j < 8; j++) {
            const float snd = par ? own[j] : own[7 - j];
            b[8 + j] = __shfl_xor_sync(0xffffffffu, snd, 1);
        }

        // wv on lower-half of b: even -> logical wv[0..7]; odd -> wv[15..8]
#pragma unroll
        for (int j = 0; j < 8; j++) wvh[j] = fmaf(b[j], gsv, wvh[j]);

        // triangle: 36 small + 28 mixed + 8 anti-diagonal
        int c = 0;
#pragma unroll
        for (int k = 0; k < 8; k++)
#pragma unroll
            for (int q = 0; q <= k; q++) {
                tri[c] = fmaf(b[k], b[q], tri[c]);
                c++;
            }
#pragma unroll
        for (int k = 8; k < 15; k++)
#pragma unroll
            for (int q = 0; q < 15 - k; q++) {
                tri[c] = fmaf(b[k], b[q], tri[c]);
                c++;
            }
#pragma unroll
        for (int k = 8; k < 16; k++) {
            tri[c] = fmaf(b[k], b[15 - k], tri[c]);
            c++;
        }
    }

    // butterfly over SAME-PARITY lanes (even offsets only)
#pragma unroll
    for (int off = 16; off > 1; off >>= 1) {
#pragma unroll
        for (int q = 0; q < NTRI; q++) tri[q] += __shfl_xor_sync(0xffffffffu, tri[q], off);
#pragma unroll
        for (int q = 0; q < 8; q++) wvh[q] += __shfl_xor_sync(0xffffffffu, wvh[q], off);
    }
    // stats: full butterfly (both lanes duplicated row stats -> x0.5 later)
#pragma unroll
    for (int off = 16; off > 0; off >>= 1) {
        rdr  += __shfl_xor_sync(0xffffffffu, rdr,  off);
        ld   += __shfl_xor_sync(0xffffffffu, ld,   off);
        sv2  += __shfl_xor_sync(0xffffffffu, sv2,  off);
        ssg  += __shfl_xor_sync(0xffffffffu, ssg,  off);
        srel += __shfl_xor_sync(0xffffffffu, srel, off);
        smin  = fminf(smin, __shfl_xor_sync(0xffffffffu, smin, off));
    }

    __shared__ float wp [NW][2 * NTRI];   // [w][par*72 + r]
    __shared__ float wpv[NW][16];         // [w][par*8 + j]
    __shared__ float wps[NW][6];
    __shared__ float sM[16][17];
    __shared__ float sw[16];
    __shared__ float srd[2];

    {
        const int w = t >> 5, l = t & 31, g = l >> 1, h = l & 1;
        for (int r = g; r < NTRI; r += 16) wp[w][h * NTRI + r] = tri[r];
        if (g < 8) wpv[w][h * 8 + g] = wvh[g];
        if (l == 0) {
            wps[w][0] = rdr;  wps[w][1] = ld;  wps[w][2] = sv2;
            wps[w][3] = ssg;  wps[w][4] = srel; wps[w][5] = smin;
        }
    }
    __syncthreads();

    // ---- merge: rebuild M(16x16) from the two entry classes ----
    if (t < 136) {
        // decode (k,q), q<=k, from linear index t
        int k = 0;
        while ((k + 1) * (k + 2) / 2 <= t) k++;
        const int q = t - k * (k + 1) / 2;

        float val;
        if (k + q == 15 && k >= 8) {                     // anti-diag (dup -> x0.5)
            const int r = 64 + (k - 8);
            float s0 = 0.0f;
#pragma unroll
            for (int w = 0; w < NW; w++) s0 += wp[w][r] + wp[w][NTRI + r];
            val = 0.5f * s0;
        } else {
            int cls, r;
            if (k <= 7)            { cls = 0; r = k * (k + 1) / 2 + q; }
            else if (q >= 8)       { cls = 1; const int kk = 15 - q;
                                     r = kk * (kk + 1) / 2 + (15 - k); }
            else if (k + q < 15)   { cls = 0; r = 64 - (15 - k) * (16 - k) / 2 + q; }
            else /* k+q > 15 */    { cls = 1; r = 64 - q * (q + 1) / 2 + (15 - k); }
            float s0 = 0.0f;
#pragma unroll
            for (int w = 0; w < NW; w++) s0 += wp[w][cls * NTRI + r];
            val = s0;
        }
        if (k == q) val += 1.0f + 1e-6f;                 // I + jitter
        sM[k][q] = val;
        sM[q][k] = val;
    } else if (t < 152) {                                // wv merge
        const int k = t - 136;
        const int src = (k < 8) ? k : (8 + (15 - k));
        float s0 = 0.0f;
#pragma unroll
        for (int w = 0; w < NW; w++) s0 += wpv[w][src];
        sw[k] = s0;
    } else if (t < 158) {                                // stats merge
        const int c = t - 152;
        if (c == 5) {
            float s0 = 3.402823466e38f;
#pragma unroll
            for (int w = 0; w < NW; w++) s0 = fminf(s0, wps[w][5]);
            g_sc[pat][5] = s0;
        } else {
            float s0 = 0.0f;
#pragma unroll
            for (int w = 0; w < NW; w++) s0 += wps[w][c];
            if (c == 0) { s0 *= 0.5f; srd[0] = s0; }     // rdr (pair-dup)
            if (c == 1) { s0 *= 0.5f; srd[1] = s0; }     // logdetD (pair-dup)
            if (c == 3 || c == 4) s0 *= 0.5f;            // ssg, srel (pair-dup)
            g_sc[pat][c] = s0;                           // sv2 (c==2) not dup'd
        }
    }
    __syncthreads();

    // ---- Cholesky + solve + NLL (warp 0) ----
    if (t < 32) {
        for (int j = 0; j < 16; j++) {
            if (t == j) sM[j][j] = sqrtf(sM[j][j]);
            __syncwarp();
            if (t > j && t < 16) sM[t][j] = sM[t][j] / sM[j][j];
            __syncwarp();
            if (t > j && t < 16) {
                const float lij = sM[t][j];
                for (int q = j + 1; q <= t; q++)
                    sM[t][q] -= lij * sM[q][j];
            }
            __syncwarp();
        }
        __syncwarp();
        if (t == 0) {
            float y[16];
            float yy = 0.0f, ldm = 0.0f;
            for (int r2 = 0; r2 < 16; r2++) {
                float acc = sw[r2];
                for (int q = 0; q < r2; q++) acc -= sM[r2][q] * y[q];
                y[r2] = acc / sM[r2][r2];
                yy  = fmaf(y[r2], y[r2], yy);
                ldm += __logf(sM[r2][r2]);
            }
            const float quad = srd[0] - yy;
            g_nll[pat] = 0.5f * (quad + srd[1] + 2.0f * ldm + GCONST)
                         * (1.0f / (float)DD);
        }
    }
}

// ---------------------------------------------------------------------------
// Boundary loss over unpatchify(mu)
// ---------------------------------------------------------------------------
__global__ void __launch_bounds__(256) boundary_kernel(const float* __restrict__ mu)
{
    int e = blockIdx.x * 256 + threadIdx.x;     // [0, 172032)
    int q = e;
    const bool isdy = (q < 86016);
    if (!isdy) q -= 86016;
    const int xw = q & 511;  q >>= 9;
    const int c  = q % 3;    q /= 3;
    const int b  = q & 7;    q >>= 3;
    const int tb = q;                            // 0..6 -> boundary at 64*(tb+1)

    size_t ia, ib;
    if (isdy) {
        const int gx = xw >> 6, px = xw & 63;
        ia = (size_t)(b * 64 + (tb + 1) * 8 + gx) * DD + c * 4096 + px;
        ib = (size_t)(b * 64 +  tb      * 8 + gx) * DD + c * 4096 + 4032 + px;
    } else {
        const int gy = xw >> 6, py = xw & 63;
        ia = (size_t)(b * 64 + gy * 8 + tb + 1) * DD + c * 4096 + py * 64;
        ib = (size_t)(b * 64 + gy * 8 + tb    ) * DD + c * 4096 + py * 64 + 63;
    }
    const float dif = mu[ia] - mu[ib];
    float v = dif * dif;

#pragma unroll
    for (int off = 16; off > 0; off >>= 1) v += __shfl_xor_sync(0xffffffffu, v, off);
    __shared__ float sred[8];
    if ((threadIdx.x & 31) == 0) sred[threadIdx.x >> 5] = v;
    __syncthreads();
    if (threadIdx.x < 8) {
        float s = sred[threadIdx.x];
#pragma unroll
        for (int off = 4; off > 0; off >>= 1) s += __shfl_xor_sync(0xffu, s, off);
        if (threadIdx.x == 0) g_bp[blockIdx.x] = s;
    }
}

// ---------------------------------------------------------------------------
// Final reduction
// ---------------------------------------------------------------------------
__global__ void __launch_bounds__(512) final_kernel(float* __restrict__ out, int out_size)
{
    const int t = threadIdx.x;       // 512 threads
    float nl = g_nll[t];
    float bs = (t < BBLK) ? g_bp[t] : 0.0f;
    if (t + 512 < BBLK) bs += g_bp[t + 512];

    float sv2 = g_sc[t][2], ssg = g_sc[t][3], srel = g_sc[t][4];
    float rmin = g_sc[t][5];

#pragma unroll
    for (int off = 16; off > 0; off >>= 1) {
        nl   += __shfl_xor_sync(0xffffffffu, nl,   off);
        bs   += __shfl_xor_sync(0xffffffffu, bs,   off);
        sv2  += __shfl_xor_sync(0xffffffffu, sv2,  off);
        ssg  += __shfl_xor_sync(0xffffffffu, ssg,  off);
        srel += __shfl_xor_sync(0xffffffffu, srel, off);
        rmin  = fminf(rmin, __shfl_xor_sync(0xffffffffu, rmin, off));
    }
    __shared__ float sm[16][6];
    if ((t & 31) == 0) {
        const int w = t >> 5;
        sm[w][0] = nl; sm[w][1] = bs; sm[w][2] = sv2;
        sm[w][3] = ssg; sm[w][4] = srel; sm[w][5] = rmin;
    }
    __syncthreads();
    if (t < 16) {
        float a0 = sm[t][0], a1 = sm[t][1], a2 = sm[t][2];
        float a3 = sm[t][3], a4 = sm[t][4], a5 = sm[t][5];
#pragma unroll
        for (int off = 8; off > 0; off >>= 1) {
            a0 += __shfl_xor_sync(0xffffu, a0, off);
            a1 += __shfl_xor_sync(0xffffu, a1, off);
            a2 += __shfl_xor_sync(0xffffu, a2, off);
            a3 += __shfl_xor_sync(0xffffu, a3, off);
            a4 += __shfl_xor_sync(0xffffu, a4, off);
            a5  = fminf(a5, __shfl_xor_sync(0xffffu, a5, off));
        }
        if (t == 0) {
            const float recon = a0 * (1.0f / 512.0f);
            const float bnd   = a1 * (1.0f / 172032.0f);
            const float rank  = a2 * (1.0f / 100663296.0f);
            const float msig  = a3 * (1.0f / 6291456.0f);
            const float sgp2  = a4 * (1.0f / 6291456.0f);
            out[0] = recon + 0.1f * bnd + 0.01f * rank + 0.05f * sgp2;
            out[1] = recon;
            out[2] = bnd;
            out[3] = rank;
            out[4] = sgp2;
            out[5] = msig;
            out[6] = a5;
        }
    }
    __syncthreads();
    for (int q = t + ((t >= 7) ? 0 : 512); q < out_size; q += 512)
        if (q >= 7) out[q] = 0.0f;
}

// ---------------------------------------------------------------------------
extern "C" void kernel_launch(void* const* d_in, const int* in_sizes, int n_in,
                              void* d_out, int out_size)
{
    int vi = 3;
    for (int idx = 0; idx < n_in; idx++)
        if (in_sizes[idx] == 100663296) vi = idx;
    const float* rest[3] = {nullptr, nullptr, nullptr};
    int m = 0;
    for (int idx = 0; idx < n_in && m < 3; idx++)
        if (idx != vi) rest[m++] = (const float*)d_in[idx];
    const float* x0 = rest[0];
    const float* mu = rest[1];
    const float* sg = rest[2];
    const float* V  = (const float*)d_in[vi];

    boundary_kernel<<<BBLK, 256>>>(mu);
    pass1_kernel<<<BN, T1>>>(x0, mu, sg, V);
    final_kernel<<<1, 512>>>((float*)d_out, out_size);
}